// round 2
// baseline (speedup 1.0000x reference)
#include <cuda_runtime.h>
#include <math.h>

// ---------------- problem constants ----------------
#define B_   8
#define NE_  1024
#define NO_  8
#define D_   1024
#define E_   8
#define H_   2048
#define O_   1024
#define NH_  8
#define HD_  128
#define FH_  4096
#define T_   8192            // B_*NE_ tokens

// ---------------- GEMM tiling ----------------
#define TM 128
#define TN 128
#define KT 8

// MoE slot binning: per-expert slot ranges padded to multiples of TM so each
// 128-row tile belongs to exactly one expert.
#define MAXTILES 136                     // ceil((16384 + 8*127)/128)
#define SLOTMAX  (MAXTILES * TM)         // 17408

// ---------------- device scratch (no allocation allowed) ----------------
__device__ float g_xagg[(size_t)T_ * D_];               // pooled tokens  (32 MB)
__device__ float g_ent [(size_t)T_ * O_];               // MoE output     (32 MB)
__device__ int   g_topi[T_ * 2];
__device__ float g_gate[T_ * 2];
__device__ int   g_cnt [E_];
__device__ int   g_off [E_ + 1];
__device__ int   g_fill[E_];
__device__ int   g_tile_e[MAXTILES];
__device__ int   g_slot_tok[SLOTMAX];
__device__ float g_slot_gw [SLOTMAX];
__device__ float g_hbuf[(size_t)SLOTMAX * H_];          // 142.6 MB (also reused as FFN hidden 8192x4096)
__device__ float g_q  [(size_t)T_ * O_];
__device__ float g_k  [(size_t)T_ * O_];
__device__ float g_v  [(size_t)T_ * O_];
__device__ float g_scores[(size_t)B_ * NH_ * NE_ * NE_]; // 256 MB
__device__ float g_ctx[(size_t)T_ * O_];
__device__ float g_rel[(size_t)T_ * O_];

// ---------------- shared 8x8 microtile compute ----------------
__device__ __forceinline__ void compute_tile(const float As[KT][TM],
                                             const float Bs[KT][TN],
                                             float acc[8][8], int row0, int col0)
{
#pragma unroll
    for (int k = 0; k < KT; k++) {
        float4 a0 = *(const float4*)&As[k][row0];
        float4 a1 = *(const float4*)&As[k][row0 + 4];
        float4 b0 = *(const float4*)&Bs[k][col0];
        float4 b1 = *(const float4*)&Bs[k][col0 + 4];
        float ar[8] = {a0.x, a0.y, a0.z, a0.w, a1.x, a1.y, a1.z, a1.w};
        float br[8] = {b0.x, b0.y, b0.z, b0.w, b1.x, b1.y, b1.z, b1.w};
#pragma unroll
        for (int i = 0; i < 8; i++)
#pragma unroll
            for (int j = 0; j < 8; j++)
                acc[i][j] = fmaf(ar[i], br[j], acc[i][j]);
    }
}

// ---------------- init (zero / reset scratch) ----------------
__global__ void init_kernel()
{
    size_t i      = (size_t)blockIdx.x * blockDim.x + threadIdx.x;
    size_t stride = (size_t)gridDim.x * blockDim.x;
    for (size_t j = i; j < (size_t)T_ * O_; j += stride) g_ent[j] = 0.f;
    for (size_t j = i; j < (size_t)SLOTMAX; j += stride) g_slot_tok[j] = -1;
    if (i < E_) { g_cnt[i] = 0; g_fill[i] = 0; }
}

// ---------------- 1) entity attention pooling ----------------
__global__ void __launch_bounds__(256) pool_kernel(const float* __restrict__ x,
                                                   const float* __restrict__ attn_w)
{
    const int t   = blockIdx.x;
    const int tid = threadIdx.x;
    const float* base = x + (size_t)t * NO_ * D_;
    float4 aw = ((const float4*)attn_w)[tid];

    float p[NO_];
#pragma unroll
    for (int o = 0; o < NO_; o++) {
        float4 xv = ((const float4*)(base + (size_t)o * D_))[tid];
        p[o] = xv.x * aw.x + xv.y * aw.y + xv.z * aw.z + xv.w * aw.w;
    }
#pragma unroll
    for (int off = 16; off; off >>= 1)
#pragma unroll
        for (int o = 0; o < NO_; o++)
            p[o] += __shfl_down_sync(0xffffffffu, p[o], off);

    __shared__ float sm[NO_][8];
    __shared__ float wsh[NO_];
    const int w = tid >> 5;
    if ((tid & 31) == 0)
#pragma unroll
        for (int o = 0; o < NO_; o++) sm[o][w] = p[o];
    __syncthreads();
    if (tid == 0) {
        float l[NO_];
#pragma unroll
        for (int o = 0; o < NO_; o++) {
            float s = 0.f;
#pragma unroll
            for (int ww = 0; ww < 8; ww++) s += sm[o][ww];
            l[o] = s;
        }
        float mx = l[0];
#pragma unroll
        for (int o = 1; o < NO_; o++) mx = fmaxf(mx, l[o]);
        float ssum = 0.f;
#pragma unroll
        for (int o = 0; o < NO_; o++) { float e = expf(l[o] - mx); wsh[o] = e; ssum += e; }
        float inv = 1.f / ssum;
#pragma unroll
        for (int o = 0; o < NO_; o++) wsh[o] *= inv;
    }
    __syncthreads();

    float4 outv = make_float4(0.f, 0.f, 0.f, 0.f);
#pragma unroll
    for (int o = 0; o < NO_; o++) {
        float4 xv = ((const float4*)(base + (size_t)o * D_))[tid];
        float wo = wsh[o];
        outv.x = fmaf(wo, xv.x, outv.x);
        outv.y = fmaf(wo, xv.y, outv.y);
        outv.z = fmaf(wo, xv.z, outv.z);
        outv.w = fmaf(wo, xv.w, outv.w);
    }
    ((float4*)(g_xagg + (size_t)t * D_))[tid] = outv;
}

// ---------------- 2a) gating: logits, top-2, renormalized gates, counts -------
__global__ void __launch_bounds__(256) gate_kernel(const float* __restrict__ gW,
                                                   const float* __restrict__ gb)
{
    const int t   = blockIdx.x;
    const int tid = threadIdx.x;
    float4 xv = ((const float4*)(g_xagg + (size_t)t * D_))[tid];
    float xs[4] = {xv.x, xv.y, xv.z, xv.w};
    const float* gr = gW + (size_t)tid * 4 * E_;

    float acc[E_];
#pragma unroll
    for (int e = 0; e < E_; e++) acc[e] = 0.f;
#pragma unroll
    for (int r = 0; r < 4; r++) {
        float4 w0 = *(const float4*)(gr + r * E_);
        float4 w1 = *(const float4*)(gr + r * E_ + 4);
        acc[0] = fmaf(xs[r], w0.x, acc[0]);
        acc[1] = fmaf(xs[r], w0.y, acc[1]);
        acc[2] = fmaf(xs[r], w0.z, acc[2]);
        acc[3] = fmaf(xs[r], w0.w, acc[3]);
        acc[4] = fmaf(xs[r], w1.x, acc[4]);
        acc[5] = fmaf(xs[r], w1.y, acc[5]);
        acc[6] = fmaf(xs[r], w1.z, acc[6]);
        acc[7] = fmaf(xs[r], w1.w, acc[7]);
    }
#pragma unroll
    for (int off = 16; off; off >>= 1)
#pragma unroll
        for (int e = 0; e < E_; e++)
            acc[e] += __shfl_down_sync(0xffffffffu, acc[e], off);

    __shared__ float sm[E_][8];
    const int w = tid >> 5;
    if ((tid & 31) == 0)
#pragma unroll
        for (int e = 0; e < E_; e++) sm[e][w] = acc[e];
    __syncthreads();
    if (tid == 0) {
        float l[E_];
#pragma unroll
        for (int e = 0; e < E_; e++) {
            float s = gb[e];
#pragma unroll
            for (int ww = 0; ww < 8; ww++) s += sm[e][ww];
            l[e] = s;
        }
        int i0 = 0;
#pragma unroll
        for (int e = 1; e < E_; e++) if (l[e] > l[i0]) i0 = e;
        int i1 = -1;
#pragma unroll
        for (int e = 0; e < E_; e++)
            if (e != i0 && (i1 < 0 || l[e] > l[i1])) i1 = e;
        // renormalized top-2 softmax gates: denominators cancel exactly
        float g0 = 1.f / (1.f + expf(l[i1] - l[i0]));
        g_topi[2 * t]     = i0;
        g_topi[2 * t + 1] = i1;
        g_gate[2 * t]     = g0;
        g_gate[2 * t + 1] = 1.f - g0;
        atomicAdd(&g_cnt[i0], 1);
        atomicAdd(&g_cnt[i1], 1);
    }
}

// ---------------- 2b) exclusive scan with 128-alignment + tile->expert map ----
__global__ void scan_kernel()
{
    if (threadIdx.x == 0 && blockIdx.x == 0) {
        int off = 0;
        for (int e = 0; e < E_; e++) {
            g_off[e] = off;
            int tiles = (g_cnt[e] + TM - 1) / TM;
            for (int tt = 0; tt < tiles; tt++) g_tile_e[off / TM + tt] = e;
            off += tiles * TM;
        }
        g_off[E_] = off;
        for (int tt = off / TM; tt < MAXTILES; tt++) g_tile_e[tt] = -1;
    }
}

// ---------------- 2c) place assignments into expert slot bins ----------------
__global__ void place_kernel()
{
    int t = blockIdx.x * blockDim.x + threadIdx.x;
    if (t >= T_) return;
#pragma unroll
    for (int j = 0; j < 2; j++) {
        int e   = g_topi[2 * t + j];
        int pos = atomicAdd(&g_fill[e], 1);
        int s   = g_off[e] + pos;
        g_slot_tok[s] = t;
        g_slot_gw[s]  = g_gate[2 * t + j];
    }
}

// ---------------- 2d) expert GEMM1: h = relu(xagg[tok] @ eW1[e] + eb1[e]) ----
__global__ void __launch_bounds__(256) moe_gemm1(const float* __restrict__ xagg,
                                                 const float* __restrict__ eW1,
                                                 const float* __restrict__ eb1)
{
    const int e = g_tile_e[blockIdx.y];
    if (e < 0) return;
    __shared__ float As[KT][TM], Bs[KT][TN];
    const int tid = threadIdx.x;
    const int m0 = blockIdx.y * TM, n0 = blockIdx.x * TN;
    const int ar = tid >> 1, ak = (tid & 1) * 4;
    const int bk = tid >> 5, bn = (tid & 31) * 4;
    const int tokA = g_slot_tok[m0 + ar];
    const float* Ap = xagg + (size_t)((tokA >= 0) ? tokA : 0) * D_ + ak;
    const float* Bp = eW1 + (size_t)e * D_ * H_ + (size_t)bk * H_ + n0 + bn;
    const int row0 = (tid >> 4) * 8, col0 = (tid & 15) * 8;
    float acc[8][8];
#pragma unroll
    for (int i = 0; i < 8; i++)
#pragma unroll
        for (int j = 0; j < 8; j++) acc[i][j] = 0.f;

    for (int kk = 0; kk < D_; kk += KT) {
        float4 av = (tokA >= 0) ? *(const float4*)(Ap + kk)
                                : make_float4(0.f, 0.f, 0.f, 0.f);
        float4 bv = *(const float4*)(Bp + (size_t)kk * H_);
        __syncthreads();
        As[ak + 0][ar] = av.x; As[ak + 1][ar] = av.y;
        As[ak + 2][ar] = av.z; As[ak + 3][ar] = av.w;
        *(float4*)&Bs[bk][bn] = bv;
        __syncthreads();
        compute_tile(As, Bs, acc, row0, col0);
    }
#pragma unroll
    for (int i = 0; i < 8; i++) {
        float* Crow = g_hbuf + (size_t)(m0 + row0 + i) * H_ + n0 + col0;
        const float* br = eb1 + (size_t)e * H_ + n0 + col0;
#pragma unroll
        for (int j = 0; j < 8; j++)
            Crow[j] = fmaxf(acc[i][j] + br[j], 0.f);
    }
}

// ------- 2e) expert GEMM2: ent[tok] += gw * (h @ eW2[e] + eb2[e]) (scatter) ---
__global__ void __launch_bounds__(256) moe_gemm2(const float* __restrict__ eW2,
                                                 const float* __restrict__ eb2)
{
    const int e = g_tile_e[blockIdx.y];
    if (e < 0) return;
    __shared__ float As[KT][TM], Bs[KT][TN];
    const int tid = threadIdx.x;
    const int m0 = blockIdx.y * TM, n0 = blockIdx.x * TN;
    const int ar = tid >> 1, ak = (tid & 1) * 4;
    const int bk = tid >> 5, bn = (tid & 31) * 4;
    const float* Ap = g_hbuf + (size_t)(m0 + ar) * H_ + ak;
    const float* Bp = eW2 + (size_t)e * H_ * O_ + (size_t)bk * O_ + n0 + bn;
    const int row0 = (tid >> 4) * 8, col0 = (tid & 15) * 8;
    float acc[8][8];
#pragma unroll
    for (int i = 0; i < 8; i++)
#pragma unroll
        for (int j = 0; j < 8; j++) acc[i][j] = 0.f;

    for (int kk = 0; kk < H_; kk += KT) {
        float4 av = *(const float4*)(Ap + kk);
        float4 bv = *(const float4*)(Bp + (size_t)kk * O_);
        __syncthreads();
        As[ak + 0][ar] = av.x; As[ak + 1][ar] = av.y;
        As[ak + 2][ar] = av.z; As[ak + 3][ar] = av.w;
        *(float4*)&Bs[bk][bn] = bv;
        __syncthreads();
        compute_tile(As, Bs, acc, row0, col0);
    }
#pragma unroll
    for (int i = 0; i < 8; i++) {
        const int tok = g_slot_tok[m0 + row0 + i];
        if (tok < 0) continue;
        const float gw = g_slot_gw[m0 + row0 + i];
        const float* br = eb2 + (size_t)e * O_ + n0 + col0;
        float* Crow = g_ent + (size_t)tok * O_ + n0 + col0;
#pragma unroll
        for (int j = 0; j < 8; j++)
            atomicAdd(&Crow[j], gw * (acc[i][j] + br[j]));
    }
}

// ---------------- generic NN GEMM: C = act(A @ B + bias) ----------------
__global__ void __launch_bounds__(256) gemm_nn(const float* __restrict__ A, int lda,
                                               const float* __restrict__ B, int ldb,
                                               float* __restrict__ C, int ldc, int Kdim,
                                               const float* __restrict__ bias, int relu)
{
    __shared__ float As[KT][TM], Bs[KT][TN];
    const int tid = threadIdx.x;
    const int m0 = blockIdx.y * TM, n0 = blockIdx.x * TN;
    const int ar = tid >> 1, ak = (tid & 1) * 4;
    const int bk = tid >> 5, bn = (tid & 31) * 4;
    const float* Ap = A + (size_t)(m0 + ar) * lda + ak;
    const float* Bp = B + (size_t)bk * ldb + n0 + bn;
    const int row0 = (tid >> 4) * 8, col0 = (tid & 15) * 8;
    float acc[8][8];
#pragma unroll
    for (int i = 0; i < 8; i++)
#pragma unroll
        for (int j = 0; j < 8; j++) acc[i][j] = 0.f;

    for (int kk = 0; kk < Kdim; kk += KT) {
        float4 av = *(const float4*)(Ap + kk);
        float4 bv = *(const float4*)(Bp + (size_t)kk * ldb);
        __syncthreads();
        As[ak + 0][ar] = av.x; As[ak + 1][ar] = av.y;
        As[ak + 2][ar] = av.z; As[ak + 3][ar] = av.w;
        *(float4*)&Bs[bk][bn] = bv;
        __syncthreads();
        compute_tile(As, Bs, acc, row0, col0);
    }
#pragma unroll
    for (int i = 0; i < 8; i++) {
        float* Crow = C + (size_t)(m0 + row0 + i) * ldc + n0 + col0;
        const float* br = bias + n0 + col0;
#pragma unroll
        for (int j = 0; j < 8; j++) {
            float v = acc[i][j] + br[j];
            if (relu) v = fmaxf(v, 0.f);
            Crow[j] = v;
        }
    }
}

// ---------------- 3a) scores = q @ k^T (batched NT, per (b,h)) ----------------
__global__ void __launch_bounds__(256) scores_gemm()
{
    __shared__ float As[KT][TM], Bs[KT][TN];
    const int tid = threadIdx.x;
    const int bh = blockIdx.z;
    const int b = bh >> 3, h = bh & 7;
    const float* Aq = g_q + (size_t)b * NE_ * O_ + h * HD_;
    const float* Bk = g_k + (size_t)b * NE_ * O_ + h * HD_;
    float* C = g_scores + (size_t)bh * NE_ * NE_;
    const int m0 = blockIdx.y * TM, n0 = blockIdx.x * TN;
    const int ar = tid >> 1, ak = (tid & 1) * 4;
    const int bn_r = tid >> 1, bk0 = (tid & 1) * 4;
    const float* Ap  = Aq + (size_t)(m0 + ar) * O_ + ak;
    const float* Btp = Bk + (size_t)(n0 + bn_r) * O_ + bk0;
    const int row0 = (tid >> 4) * 8, col0 = (tid & 15) * 8;
    float acc[8][8];
#pragma unroll
    for (int i = 0; i < 8; i++)
#pragma unroll
        for (int j = 0; j < 8; j++) acc[i][j] = 0.f;

    for (int kk = 0; kk < HD_; kk += KT) {
        float4 av = *(const float4*)(Ap + kk);
        float4 bv = *(const float4*)(Btp + kk);
        __syncthreads();
        As[ak + 0][ar] = av.x; As[ak + 1][ar] = av.y;
        As[ak + 2][ar] = av.z; As[ak + 3][ar] = av.w;
        Bs[bk0 + 0][bn_r] = bv.x; Bs[bk0 + 1][bn_r] = bv.y;
        Bs[bk0 + 2][bn_r] = bv.z; Bs[bk0 + 3][bn_r] = bv.w;
        __syncthreads();
        compute_tile(As, Bs, acc, row0, col0);
    }
#pragma unroll
    for (int i = 0; i < 8; i++) {
        float* Crow = C + (size_t)(m0 + row0 + i) * NE_ + n0 + col0;
#pragma unroll
        for (int j = 0; j < 8; j++) Crow[j] = acc[i][j];
    }
}

// ---------------- 3b) softmax over key dim (scale folded in) ----------------
__global__ void __launch_bounds__(256) attn_softmax_kernel()
{
    const int tid = threadIdx.x;
    float* row = g_scores + (size_t)blockIdx.x * NE_;
    float4 v = ((float4*)row)[tid];
    const float sc = 0.08838834764831845f;   // 1/sqrt(128)
    v.x *= sc; v.y *= sc; v.z *= sc; v.w *= sc;

    float m = fmaxf(fmaxf(v.x, v.y), fmaxf(v.z, v.w));
#pragma unroll
    for (int off = 16; off; off >>= 1)
        m = fmaxf(m, __shfl_xor_sync(0xffffffffu, m, off));
    __shared__ float sred[8];
    const int w = tid >> 5;
    if ((tid & 31) == 0) sred[w] = m;
    __syncthreads();
    float gm = sred[0];
#pragma unroll
    for (int i = 1; i < 8; i++) gm = fmaxf(gm, sred[i]);

    float e0 = expf(v.x - gm), e1 = expf(v.y - gm);
    float e2 = expf(v.z - gm), e3 = expf(v.w - gm);
    float s = e0 + e1 + e2 + e3;
#pragma unroll
    for (int off = 16; off; off >>= 1)
        s += __shfl_xor_sync(0xffffffffu, s, off);
    __syncthreads();
    if ((tid & 31) == 0) sred[w] = s;
    __syncthreads();
    float gs = 0.f;
#pragma unroll
    for (int i = 0; i < 8; i++) gs += sred[i];
    float inv = 1.f / gs;
    ((float4*)row)[tid] = make_float4(e0 * inv, e1 * inv, e2 * inv, e3 * inv);
}

// ---------------- 3c) ctx = attn @ v (batched NN, N = HD = 128) ----------------
__global__ void __launch_bounds__(256) ctx_gemm()
{
    __shared__ float As[KT][TM], Bs[KT][TN];
    const int tid = threadIdx.x;
    const int bh = blockIdx.z;
    const int b = bh >> 3, h = bh & 7;
    const float* Aatt = g_scores + (size_t)bh * NE_ * NE_;
    const float* Bv   = g_v + (size_t)b * NE_ * O_ + h * HD_;
    float* C = g_ctx + (size_t)b * NE_ * O_ + h * HD_;
    const int m0 = blockIdx.y * TM, n0 = 0;
    const int ar = tid >> 1, ak = (tid & 1) * 4;
    const int bk = tid >> 5, bn = (tid & 31) * 4;
    const float* Ap = Aatt + (size_t)(m0 + ar) * NE_ + ak;
    const float* Bp = Bv + (size_t)bk * O_ + n0 + bn;
    const int row0 = (tid >> 4) * 8, col0 = (tid & 15) * 8;
    float acc[8][8];
#pragma unroll
    for (int i = 0; i < 8; i++)
#pragma unroll
        for (int j = 0; j < 8; j++) acc[i][j] = 0.f;

    for (int kk = 0; kk < NE_; kk += KT) {
        float4 av = *(const float4*)(Ap + kk);
        float4 bv = *(const float4*)(Bp + (size_t)kk * O_);
        __syncthreads();
        As[ak + 0][ar] = av.x; As[ak + 1][ar] = av.y;
        As[ak + 2][ar] = av.z; As[ak + 3][ar] = av.w;
        *(float4*)&Bs[bk][bn] = bv;
        __syncthreads();
        compute_tile(As, Bs, acc, row0, col0);
    }
#pragma unroll
    for (int i = 0; i < 8; i++) {
        float* Crow = C + (size_t)(m0 + row0 + i) * O_ + n0 + col0;
#pragma unroll
        for (int j = 0; j < 8; j++) Crow[j] = acc[i][j];
    }
}

// ---------------- host launcher ----------------
extern "C" void kernel_launch(void* const* d_in, const int* in_sizes, int n_in,
                              void* d_out, int out_size)
{
    const float* x      = (const float*)d_in[0];
    const float* attn_w = (const float*)d_in[1];
    const float* gate_W = (const float*)d_in[2];
    const float* gate_b = (const float*)d_in[3];
    const float* eW1    = (const float*)d_in[4];
    const float* eb1    = (const float*)d_in[5];
    const float* eW2    = (const float*)d_in[6];
    const float* eb2    = (const float*)d_in[7];
    const float* Wq     = (const float*)d_in[8];
    const float* bq     = (const float*)d_in[9];
    const float* Wk     = (const float*)d_in[10];
    const float* bk     = (const float*)d_in[11];
    const float* Wv     = (const float*)d_in[12];
    const float* bv     = (const float*)d_in[13];
    const float* Wo     = (const float*)d_in[14];
    const float* bo     = (const float*)d_in[15];
    const float* fW1    = (const float*)d_in[16];
    const float* fb1    = (const float*)d_in[17];
    const float* fW2    = (const float*)d_in[18];
    const float* fb2    = (const float*)d_in[19];
    float* out = (float*)d_out;

    float *p_xagg, *p_ent, *p_q, *p_k, *p_v, *p_ctx, *p_rel, *p_hbuf;
    cudaGetSymbolAddress((void**)&p_xagg, g_xagg);
    cudaGetSymbolAddress((void**)&p_ent,  g_ent);
    cudaGetSymbolAddress((void**)&p_q,    g_q);
    cudaGetSymbolAddress((void**)&p_k,    g_k);
    cudaGetSymbolAddress((void**)&p_v,    g_v);
    cudaGetSymbolAddress((void**)&p_ctx,  g_ctx);
    cudaGetSymbolAddress((void**)&p_rel,  g_rel);
    cudaGetSymbolAddress((void**)&p_hbuf, g_hbuf);

    // 0) reset scratch
    init_kernel<<<4096, 256>>>();
    // 1) pooling
    pool_kernel<<<T_, 256>>>(x, attn_w);
    // 2) MoE routing
    gate_kernel<<<T_, 256>>>(gate_W, gate_b);
    scan_kernel<<<1, 32>>>();
    place_kernel<<<(T_ + 255) / 256, 256>>>();
    // 2) expert MLPs (sparse, slot-binned)
    moe_gemm1<<<dim3(H_ / TN, MAXTILES), 256>>>(p_xagg, eW1, eb1);
    moe_gemm2<<<dim3(O_ / TN, MAXTILES), 256>>>(eW2, eb2);
    // 3) self-attention
    gemm_nn<<<dim3(O_ / TN, T_ / TM), 256>>>(p_ent, O_, Wq, O_, p_q, O_, O_, bq, 0);
    gemm_nn<<<dim3(O_ / TN, T_ / TM), 256>>>(p_ent, O_, Wk, O_, p_k, O_, O_, bk, 0);
    gemm_nn<<<dim3(O_ / TN, T_ / TM), 256>>>(p_ent, O_, Wv, O_, p_v, O_, O_, bv, 0);
    scores_gemm<<<dim3(NE_ / TN, NE_ / TM, B_ * NH_), 256>>>();
    attn_softmax_kernel<<<B_ * NH_ * NE_, 256>>>();
    ctx_gemm<<<dim3(1, NE_ / TM, B_ * NH_), 256>>>();
    gemm_nn<<<dim3(O_ / TN, T_ / TM), 256>>>(p_ctx, O_, Wo, O_, p_rel, O_, O_, bo, 0);
    // 4) FFN
    gemm_nn<<<dim3(FH_ / TN, T_ / TM), 256>>>(p_rel, O_, fW1, FH_, p_hbuf, FH_, O_, fb1, 1);
    gemm_nn<<<dim3(O_ / TN, T_ / TM), 256>>>(p_hbuf, FH_, fW2, O_, out, O_, FH_, fb2, 0);
}

// round 4
// speedup vs baseline: 1.0024x; 1.0024x over previous
#include <cuda_runtime.h>
#include <math.h>

// ---------------- problem constants ----------------
#define B_   8
#define NE_  1024
#define NO_  8
#define D_   1024
#define E_   8
#define H_   2048
#define O_   1024
#define NH_  8
#define HD_  128
#define FH_  4096
#define T_   8192            // B_*NE_ tokens

// ---------------- GEMM tiling ----------------
#define TM 128
#define TN 128
#define KT 8

// MoE slot binning: per-expert slot ranges padded to multiples of TM so each
// 128-row tile belongs to exactly one expert.
#define MAXTILES 136                     // ceil((16384 + 8*127)/128)
#define SLOTMAX  (MAXTILES * TM)         // 17408

// ---------------- device scratch (no allocation allowed) ----------------
__device__ float g_xagg[(size_t)T_ * D_];               // pooled tokens  (32 MB)
__device__ float g_ent [(size_t)T_ * O_];               // MoE output     (32 MB)
__device__ int   g_topi[T_ * 2];
__device__ float g_gate[T_ * 2];
__device__ int   g_cnt [E_];
__device__ int   g_off [E_ + 1];
__device__ int   g_fill[E_];
__device__ int   g_tile_e[MAXTILES];
__device__ int   g_slot_tok[SLOTMAX];
__device__ float g_slot_gw [SLOTMAX];
__device__ float g_hbuf[(size_t)SLOTMAX * H_];          // 142.6 MB (also reused as FFN hidden 8192x4096)
__device__ float g_q  [(size_t)T_ * O_];
__device__ float g_k  [(size_t)T_ * O_];
__device__ float g_v  [(size_t)T_ * O_];
__device__ float g_scores[(size_t)B_ * NH_ * NE_ * NE_]; // 256 MB
__device__ float g_ctx[(size_t)T_ * O_];
__device__ float g_rel[(size_t)T_ * O_];

// ---------------- shared 8x8 microtile compute ----------------
__device__ __forceinline__ void compute_tile(const float As[KT][TM],
                                             const float Bs[KT][TN],
                                             float acc[8][8], int row0, int col0)
{
#pragma unroll
    for (int k = 0; k < KT; k++) {
        float4 a0 = *(const float4*)&As[k][row0];
        float4 a1 = *(const float4*)&As[k][row0 + 4];
        float4 b0 = *(const float4*)&Bs[k][col0];
        float4 b1 = *(const float4*)&Bs[k][col0 + 4];
        float ar[8] = {a0.x, a0.y, a0.z, a0.w, a1.x, a1.y, a1.z, a1.w};
        float br[8] = {b0.x, b0.y, b0.z, b0.w, b1.x, b1.y, b1.z, b1.w};
#pragma unroll
        for (int i = 0; i < 8; i++)
#pragma unroll
            for (int j = 0; j < 8; j++)
                acc[i][j] = fmaf(ar[i], br[j], acc[i][j]);
    }
}

// ---------------- init (zero / reset scratch) ----------------
__global__ void init_kernel()
{
    size_t i      = (size_t)blockIdx.x * blockDim.x + threadIdx.x;
    size_t stride = (size_t)gridDim.x * blockDim.x;
    for (size_t j = i; j < (size_t)T_ * O_; j += stride) g_ent[j] = 0.f;
    for (size_t j = i; j < (size_t)SLOTMAX; j += stride) g_slot_tok[j] = -1;
    if (i < E_) { g_cnt[i] = 0; g_fill[i] = 0; }
}

// ---------------- 1) entity attention pooling ----------------
__global__ void __launch_bounds__(256) pool_kernel(const float* __restrict__ x,
                                                   const float* __restrict__ attn_w)
{
    const int t   = blockIdx.x;
    const int tid = threadIdx.x;
    const float* base = x + (size_t)t * NO_ * D_;
    float4 aw = ((const float4*)attn_w)[tid];

    float p[NO_];
#pragma unroll
    for (int o = 0; o < NO_; o++) {
        float4 xv = ((const float4*)(base + (size_t)o * D_))[tid];
        p[o] = xv.x * aw.x + xv.y * aw.y + xv.z * aw.z + xv.w * aw.w;
    }
#pragma unroll
    for (int off = 16; off; off >>= 1)
#pragma unroll
        for (int o = 0; o < NO_; o++)
            p[o] += __shfl_down_sync(0xffffffffu, p[o], off);

    __shared__ float sm[NO_][8];
    __shared__ float wsh[NO_];
    const int w = tid >> 5;
    if ((tid & 31) == 0)
#pragma unroll
        for (int o = 0; o < NO_; o++) sm[o][w] = p[o];
    __syncthreads();
    if (tid == 0) {
        float l[NO_];
#pragma unroll
        for (int o = 0; o < NO_; o++) {
            float s = 0.f;
#pragma unroll
            for (int ww = 0; ww < 8; ww++) s += sm[o][ww];
            l[o] = s;
        }
        float mx = l[0];
#pragma unroll
        for (int o = 1; o < NO_; o++) mx = fmaxf(mx, l[o]);
        float ssum = 0.f;
#pragma unroll
        for (int o = 0; o < NO_; o++) { float e = expf(l[o] - mx); wsh[o] = e; ssum += e; }
        float inv = 1.f / ssum;
#pragma unroll
        for (int o = 0; o < NO_; o++) wsh[o] *= inv;
    }
    __syncthreads();

    float4 outv = make_float4(0.f, 0.f, 0.f, 0.f);
#pragma unroll
    for (int o = 0; o < NO_; o++) {
        float4 xv = ((const float4*)(base + (size_t)o * D_))[tid];
        float wo = wsh[o];
        outv.x = fmaf(wo, xv.x, outv.x);
        outv.y = fmaf(wo, xv.y, outv.y);
        outv.z = fmaf(wo, xv.z, outv.z);
        outv.w = fmaf(wo, xv.w, outv.w);
    }
    ((float4*)(g_xagg + (size_t)t * D_))[tid] = outv;
}

// ---------------- 2a) gating: logits, top-2, renormalized gates, counts -------
__global__ void __launch_bounds__(256) gate_kernel(const float* __restrict__ gW,
                                                   const float* __restrict__ gb)
{
    const int t   = blockIdx.x;
    const int tid = threadIdx.x;
    float4 xv = ((const float4*)(g_xagg + (size_t)t * D_))[tid];
    float xs[4] = {xv.x, xv.y, xv.z, xv.w};
    const float* gr = gW + (size_t)tid * 4 * E_;

    float acc[E_];
#pragma unroll
    for (int e = 0; e < E_; e++) acc[e] = 0.f;
#pragma unroll
    for (int r = 0; r < 4; r++) {
        float4 w0 = *(const float4*)(gr + r * E_);
        float4 w1 = *(const float4*)(gr + r * E_ + 4);
        acc[0] = fmaf(xs[r], w0.x, acc[0]);
        acc[1] = fmaf(xs[r], w0.y, acc[1]);
        acc[2] = fmaf(xs[r], w0.z, acc[2]);
        acc[3] = fmaf(xs[r], w0.w, acc[3]);
        acc[4] = fmaf(xs[r], w1.x, acc[4]);
        acc[5] = fmaf(xs[r], w1.y, acc[5]);
        acc[6] = fmaf(xs[r], w1.z, acc[6]);
        acc[7] = fmaf(xs[r], w1.w, acc[7]);
    }
#pragma unroll
    for (int off = 16; off; off >>= 1)
#pragma unroll
        for (int e = 0; e < E_; e++)
            acc[e] += __shfl_down_sync(0xffffffffu, acc[e], off);

    __shared__ float sm[E_][8];
    const int w = tid >> 5;
    if ((tid & 31) == 0)
#pragma unroll
        for (int e = 0; e < E_; e++) sm[e][w] = acc[e];
    __syncthreads();
    if (tid == 0) {
        float l[E_];
#pragma unroll
        for (int e = 0; e < E_; e++) {
            float s = gb[e];
#pragma unroll
            for (int ww = 0; ww < 8; ww++) s += sm[e][ww];
            l[e] = s;
        }
        int i0 = 0;
#pragma unroll
        for (int e = 1; e < E_; e++) if (l[e] > l[i0]) i0 = e;
        int i1 = -1;
#pragma unroll
        for (int e = 0; e < E_; e++)
            if (e != i0 && (i1 < 0 || l[e] > l[i1])) i1 = e;
        // renormalized top-2 softmax gates: denominators cancel exactly
        float g0 = 1.f / (1.f + expf(l[i1] - l[i0]));
        g_topi[2 * t]     = i0;
        g_topi[2 * t + 1] = i1;
        g_gate[2 * t]     = g0;
        g_gate[2 * t + 1] = 1.f - g0;
        atomicAdd(&g_cnt[i0], 1);
        atomicAdd(&g_cnt[i1], 1);
    }
}

// ---------------- 2b) exclusive scan with 128-alignment + tile->expert map ----
__global__ void scan_kernel()
{
    if (threadIdx.x == 0 && blockIdx.x == 0) {
        int off = 0;
        for (int e = 0; e < E_; e++) {
            g_off[e] = off;
            int tiles = (g_cnt[e] + TM - 1) / TM;
            for (int tt = 0; tt < tiles; tt++) g_tile_e[off / TM + tt] = e;
            off += tiles * TM;
        }
        g_off[E_] = off;
        for (int tt = off / TM; tt < MAXTILES; tt++) g_tile_e[tt] = -1;
    }
}

// ---------------- 2c) place assignments into expert slot bins ----------------
__global__ void place_kernel()
{
    int t = blockIdx.x * blockDim.x + threadIdx.x;
    if (t >= T_) return;
#pragma unroll
    for (int j = 0; j < 2; j++) {
        int e   = g_topi[2 * t + j];
        int pos = atomicAdd(&g_fill[e], 1);
        int s   = g_off[e] + pos;
        g_slot_tok[s] = t;
        g_slot_gw[s]  = g_gate[2 * t + j];
    }
}

// ---------------- 2d) expert GEMM1: h = relu(xagg[tok] @ eW1[e] + eb1[e]) ----
__global__ void __launch_bounds__(256) moe_gemm1(const float* __restrict__ xagg,
                                                 const float* __restrict__ eW1,
                                                 const float* __restrict__ eb1)
{
    const int e = g_tile_e[blockIdx.y];
    if (e < 0) return;
    __shared__ float As[KT][TM], Bs[KT][TN];
    const int tid = threadIdx.x;
    const int m0 = blockIdx.y * TM, n0 = blockIdx.x * TN;
    const int ar = tid >> 1, ak = (tid & 1) * 4;
    const int bk = tid >> 5, bn = (tid & 31) * 4;
    const int tokA = g_slot_tok[m0 + ar];
    const float* Ap = xagg + (size_t)((tokA >= 0) ? tokA : 0) * D_ + ak;
    const float* Bp = eW1 + (size_t)e * D_ * H_ + (size_t)bk * H_ + n0 + bn;
    const int row0 = (tid >> 4) * 8, col0 = (tid & 15) * 8;
    float acc[8][8];
#pragma unroll
    for (int i = 0; i < 8; i++)
#pragma unroll
        for (int j = 0; j < 8; j++) acc[i][j] = 0.f;

    for (int kk = 0; kk < D_; kk += KT) {
        float4 av = (tokA >= 0) ? *(const float4*)(Ap + kk)
                                : make_float4(0.f, 0.f, 0.f, 0.f);
        float4 bv = *(const float4*)(Bp + (size_t)kk * H_);
        __syncthreads();
        As[ak + 0][ar] = av.x; As[ak + 1][ar] = av.y;
        As[ak + 2][ar] = av.z; As[ak + 3][ar] = av.w;
        *(float4*)&Bs[bk][bn] = bv;
        __syncthreads();
        compute_tile(As, Bs, acc, row0, col0);
    }
#pragma unroll
    for (int i = 0; i < 8; i++) {
        float* Crow = g_hbuf + (size_t)(m0 + row0 + i) * H_ + n0 + col0;
        const float* br = eb1 + (size_t)e * H_ + n0 + col0;
#pragma unroll
        for (int j = 0; j < 8; j++)
            Crow[j] = fmaxf(acc[i][j] + br[j], 0.f);
    }
}

// ------- 2e) expert GEMM2: ent[tok] += gw * (h @ eW2[e] + eb2[e]) (scatter) ---
__global__ void __launch_bounds__(256) moe_gemm2(const float* __restrict__ eW2,
                                                 const float* __restrict__ eb2)
{
    const int e = g_tile_e[blockIdx.y];
    if (e < 0) return;
    __shared__ float As[KT][TM], Bs[KT][TN];
    const int tid = threadIdx.x;
    const int m0 = blockIdx.y * TM, n0 = blockIdx.x * TN;
    const int ar = tid >> 1, ak = (tid & 1) * 4;
    const int bk = tid >> 5, bn = (tid & 31) * 4;
    const float* Ap = g_hbuf + (size_t)(m0 + ar) * H_ + ak;
    const float* Bp = eW2 + (size_t)e * H_ * O_ + (size_t)bk * O_ + n0 + bn;
    const int row0 = (tid >> 4) * 8, col0 = (tid & 15) * 8;
    float acc[8][8];
#pragma unroll
    for (int i = 0; i < 8; i++)
#pragma unroll
        for (int j = 0; j < 8; j++) acc[i][j] = 0.f;

    for (int kk = 0; kk < H_; kk += KT) {
        float4 av = *(const float4*)(Ap + kk);
        float4 bv = *(const float4*)(Bp + (size_t)kk * O_);
        __syncthreads();
        As[ak + 0][ar] = av.x; As[ak + 1][ar] = av.y;
        As[ak + 2][ar] = av.z; As[ak + 3][ar] = av.w;
        *(float4*)&Bs[bk][bn] = bv;
        __syncthreads();
        compute_tile(As, Bs, acc, row0, col0);
    }
#pragma unroll
    for (int i = 0; i < 8; i++) {
        const int tok = g_slot_tok[m0 + row0 + i];
        if (tok < 0) continue;
        const float gw = g_slot_gw[m0 + row0 + i];
        const float* br = eb2 + (size_t)e * O_ + n0 + col0;
        float* Crow = g_ent + (size_t)tok * O_ + n0 + col0;
#pragma unroll
        for (int j = 0; j < 8; j++)
            atomicAdd(&Crow[j], gw * (acc[i][j] + br[j]));
    }
}

// ---------------- generic NN GEMM: C = act(A @ B + bias) ----------------
__global__ void __launch_bounds__(256) gemm_nn(const float* __restrict__ A, int lda,
                                               const float* __restrict__ B, int ldb,
                                               float* __restrict__ C, int ldc, int Kdim,
                                               const float* __restrict__ bias, int relu)
{
    __shared__ float As[KT][TM], Bs[KT][TN];
    const int tid = threadIdx.x;
    const int m0 = blockIdx.y * TM, n0 = blockIdx.x * TN;
    const int ar = tid >> 1, ak = (tid & 1) * 4;
    const int bk = tid >> 5, bn = (tid & 31) * 4;
    const float* Ap = A + (size_t)(m0 + ar) * lda + ak;
    const float* Bp = B + (size_t)bk * ldb + n0 + bn;
    const int row0 = (tid >> 4) * 8, col0 = (tid & 15) * 8;
    float acc[8][8];
#pragma unroll
    for (int i = 0; i < 8; i++)
#pragma unroll
        for (int j = 0; j < 8; j++) acc[i][j] = 0.f;

    for (int kk = 0; kk < Kdim; kk += KT) {
        float4 av = *(const float4*)(Ap + kk);
        float4 bv = *(const float4*)(Bp + (size_t)kk * ldb);
        __syncthreads();
        As[ak + 0][ar] = av.x; As[ak + 1][ar] = av.y;
        As[ak + 2][ar] = av.z; As[ak + 3][ar] = av.w;
        *(float4*)&Bs[bk][bn] = bv;
        __syncthreads();
        compute_tile(As, Bs, acc, row0, col0);
    }
#pragma unroll
    for (int i = 0; i < 8; i++) {
        float* Crow = C + (size_t)(m0 + row0 + i) * ldc + n0 + col0;
        const float* br = bias + n0 + col0;
#pragma unroll
        for (int j = 0; j < 8; j++) {
            float v = acc[i][j] + br[j];
            if (relu) v = fmaxf(v, 0.f);
            Crow[j] = v;
        }
    }
}

// ---------------- 3a) scores = q @ k^T (batched NT, per (b,h)) ----------------
__global__ void __launch_bounds__(256) scores_gemm()
{
    __shared__ float As[KT][TM], Bs[KT][TN];
    const int tid = threadIdx.x;
    const int bh = blockIdx.z;
    const int b = bh >> 3, h = bh & 7;
    const float* Aq = g_q + (size_t)b * NE_ * O_ + h * HD_;
    const float* Bk = g_k + (size_t)b * NE_ * O_ + h * HD_;
    float* C = g_scores + (size_t)bh * NE_ * NE_;
    const int m0 = blockIdx.y * TM, n0 = blockIdx.x * TN;
    const int ar = tid >> 1, ak = (tid & 1) * 4;
    const int bn_r = tid >> 1, bk0 = (tid & 1) * 4;
    const float* Ap  = Aq + (size_t)(m0 + ar) * O_ + ak;
    const float* Btp = Bk + (size_t)(n0 + bn_r) * O_ + bk0;
    const int row0 = (tid >> 4) * 8, col0 = (tid & 15) * 8;
    float acc[8][8];
#pragma unroll
    for (int i = 0; i < 8; i++)
#pragma unroll
        for (int j = 0; j < 8; j++) acc[i][j] = 0.f;

    for (int kk = 0; kk < HD_; kk += KT) {
        float4 av = *(const float4*)(Ap + kk);
        float4 bv = *(const float4*)(Btp + kk);
        __syncthreads();
        As[ak + 0][ar] = av.x; As[ak + 1][ar] = av.y;
        As[ak + 2][ar] = av.z; As[ak + 3][ar] = av.w;
        Bs[bk0 + 0][bn_r] = bv.x; Bs[bk0 + 1][bn_r] = bv.y;
        Bs[bk0 + 2][bn_r] = bv.z; Bs[bk0 + 3][bn_r] = bv.w;
        __syncthreads();
        compute_tile(As, Bs, acc, row0, col0);
    }
#pragma unroll
    for (int i = 0; i < 8; i++) {
        float* Crow = C + (size_t)(m0 + row0 + i) * NE_ + n0 + col0;
#pragma unroll
        for (int j = 0; j < 8; j++) Crow[j] = acc[i][j];
    }
}

// ---------------- 3b) softmax over key dim (scale folded in) ----------------
__global__ void __launch_bounds__(256) attn_softmax_kernel()
{
    const int tid = threadIdx.x;
    float* row = g_scores + (size_t)blockIdx.x * NE_;
    float4 v = ((float4*)row)[tid];
    const float sc = 0.08838834764831845f;   // 1/sqrt(128)
    v.x *= sc; v.y *= sc; v.z *= sc; v.w *= sc;

    float m = fmaxf(fmaxf(v.x, v.y), fmaxf(v.z, v.w));
#pragma unroll
    for (int off = 16; off; off >>= 1)
        m = fmaxf(m, __shfl_xor_sync(0xffffffffu, m, off));
    __shared__ float sred[8];
    const int w = tid >> 5;
    if ((tid & 31) == 0) sred[w] = m;
    __syncthreads();
    float gm = sred[0];
#pragma unroll
    for (int i = 1; i < 8; i++) gm = fmaxf(gm, sred[i]);

    float e0 = expf(v.x - gm), e1 = expf(v.y - gm);
    float e2 = expf(v.z - gm), e3 = expf(v.w - gm);
    float s = e0 + e1 + e2 + e3;
#pragma unroll
    for (int off = 16; off; off >>= 1)
        s += __shfl_xor_sync(0xffffffffu, s, off);
    __syncthreads();
    if ((tid & 31) == 0) sred[w] = s;
    __syncthreads();
    float gs = 0.f;
#pragma unroll
    for (int i = 0; i < 8; i++) gs += sred[i];
    float inv = 1.f / gs;
    ((float4*)row)[tid] = make_float4(e0 * inv, e1 * inv, e2 * inv, e3 * inv);
}

// ---------------- 3c) ctx = attn @ v (batched NN, N = HD = 128) ----------------
__global__ void __launch_bounds__(256) ctx_gemm()
{
    __shared__ float As[KT][TM], Bs[KT][TN];
    const int tid = threadIdx.x;
    const int bh = blockIdx.z;
    const int b = bh >> 3, h = bh & 7;
    const float* Aatt = g_scores + (size_t)bh * NE_ * NE_;
    const float* Bv   = g_v + (size_t)b * NE_ * O_ + h * HD_;
    float* C = g_ctx + (size_t)b * NE_ * O_ + h * HD_;
    const int m0 = blockIdx.y * TM, n0 = 0;
    const int ar = tid >> 1, ak = (tid & 1) * 4;
    const int bk = tid >> 5, bn = (tid & 31) * 4;
    const float* Ap = Aatt + (size_t)(m0 + ar) * NE_ + ak;
    const float* Bp = Bv + (size_t)bk * O_ + n0 + bn;
    const int row0 = (tid >> 4) * 8, col0 = (tid & 15) * 8;
    float acc[8][8];
#pragma unroll
    for (int i = 0; i < 8; i++)
#pragma unroll
        for (int j = 0; j < 8; j++) acc[i][j] = 0.f;

    for (int kk = 0; kk < NE_; kk += KT) {
        float4 av = *(const float4*)(Ap + kk);
        float4 bv = *(const float4*)(Bp + (size_t)kk * O_);
        __syncthreads();
        As[ak + 0][ar] = av.x; As[ak + 1][ar] = av.y;
        As[ak + 2][ar] = av.z; As[ak + 3][ar] = av.w;
        *(float4*)&Bs[bk][bn] = bv;
        __syncthreads();
        compute_tile(As, Bs, acc, row0, col0);
    }
#pragma unroll
    for (int i = 0; i < 8; i++) {
        float* Crow = C + (size_t)(m0 + row0 + i) * O_ + n0 + col0;
#pragma unroll
        for (int j = 0; j < 8; j++) Crow[j] = acc[i][j];
    }
}

// ---------------- host launcher ----------------
extern "C" void kernel_launch(void* const* d_in, const int* in_sizes, int n_in,
                              void* d_out, int out_size)
{
    const float* x      = (const float*)d_in[0];
    const float* attn_w = (const float*)d_in[1];
    const float* gate_W = (const float*)d_in[2];
    const float* gate_b = (const float*)d_in[3];
    const float* eW1    = (const float*)d_in[4];
    const float* eb1    = (const float*)d_in[5];
    const float* eW2    = (const float*)d_in[6];
    const float* eb2    = (const float*)d_in[7];
    const float* Wq     = (const float*)d_in[8];
    const float* bq     = (const float*)d_in[9];
    const float* Wk     = (const float*)d_in[10];
    const float* bk     = (const float*)d_in[11];
    const float* Wv     = (const float*)d_in[12];
    const float* bv     = (const float*)d_in[13];
    const float* Wo     = (const float*)d_in[14];
    const float* bo     = (const float*)d_in[15];
    const float* fW1    = (const float*)d_in[16];
    const float* fb1    = (const float*)d_in[17];
    const float* fW2    = (const float*)d_in[18];
    const float* fb2    = (const float*)d_in[19];
    float* out = (float*)d_out;

    float *p_xagg, *p_ent, *p_q, *p_k, *p_v, *p_ctx, *p_rel, *p_hbuf;
    cudaGetSymbolAddress((void**)&p_xagg, g_xagg);
    cudaGetSymbolAddress((void**)&p_ent,  g_ent);
    cudaGetSymbolAddress((void**)&p_q,    g_q);
    cudaGetSymbolAddress((void**)&p_k,    g_k);
    cudaGetSymbolAddress((void**)&p_v,    g_v);
    cudaGetSymbolAddress((void**)&p_ctx,  g_ctx);
    cudaGetSymbolAddress((void**)&p_rel,  g_rel);
    cudaGetSymbolAddress((void**)&p_hbuf, g_hbuf);

    // 0) reset scratch
    init_kernel<<<4096, 256>>>();
    // 1) pooling
    pool_kernel<<<T_, 256>>>(x, attn_w);
    // 2) MoE routing
    gate_kernel<<<T_, 256>>>(gate_W, gate_b);
    scan_kernel<<<1, 32>>>();
    place_kernel<<<(T_ + 255) / 256, 256>>>();
    // 2) expert MLPs (sparse, slot-binned)
    moe_gemm1<<<dim3(H_ / TN, MAXTILES), 256>>>(p_xagg, eW1, eb1);
    moe_gemm2<<<dim3(O_ / TN, MAXTILES), 256>>>(eW2, eb2);
    // 3) self-attention
    gemm_nn<<<dim3(O_ / TN, T_ / TM), 256>>>(p_ent, O_, Wq, O_, p_q, O_, O_, bq, 0);
    gemm_nn<<<dim3(O_ / TN, T_ / TM), 256>>>(p_ent, O_, Wk, O_, p_k, O_, O_, bk, 0);
    gemm_nn<<<dim3(O_ / TN, T_ / TM), 256>>>(p_ent, O_, Wv, O_, p_v, O_, O_, bv, 0);
    scores_gemm<<<dim3(NE_ / TN, NE_ / TM, B_ * NH_), 256>>>();
    attn_softmax_kernel<<<B_ * NH_ * NE_, 256>>>();
    ctx_gemm<<<dim3(1, NE_ / TM, B_ * NH_), 256>>>();
    gemm_nn<<<dim3(O_ / TN, T_ / TM), 256>>>(p_ctx, O_, Wo, O_, p_rel, O_, O_, bo, 0);
    // 4) FFN
    gemm_nn<<<dim3(FH_ / TN, T_ / TM), 256>>>(p_rel, O_, fW1, FH_, p_hbuf, FH_, O_, fb1, 1);
    gemm_nn<<<dim3(O_ / TN, T_ / TM), 256>>>(p_hbuf, FH_, fW2, O_, out, O_, FH_, fb2, 0);
}

// round 7
// speedup vs baseline: 2.6210x; 2.6148x over previous
#include <cuda_runtime.h>
#include <cuda_bf16.h>
#include <math.h>
#include <stdint.h>

#define B_ 8
#define NE_ 1024
#define NO_ 8
#define D_ 1024
#define E_ 8
#define H_ 2048
#define O_ 1024
#define NH_ 8
#define HD_ 128
#define FH_ 4096
#define T_ 8192
#define TM 128
#define TN 128
#define MAXTILES 136
#define SLOTMAX (MAXTILES * TM)

typedef __nv_bfloat16 bf16;

// ---------- device scratch ----------
__device__ float g_xagg[(size_t)T_ * D_];
__device__ float g_ent[(size_t)T_ * O_];
__device__ int   g_topi[T_ * 2];
__device__ float g_gate[T_ * 2];
__device__ int   g_cnt[E_], g_off[E_ + 1], g_fill[E_];
__device__ int   g_tile_e[MAXTILES];
__device__ int   g_slot_tok[SLOTMAX];
__device__ float g_slot_gw[SLOTMAX];
__device__ float g_hbuf[(size_t)SLOTMAX * H_];
__device__ float g_q[(size_t)T_ * O_], g_k[(size_t)T_ * O_], g_v[(size_t)T_ * O_];
__device__ float g_scores[(size_t)B_ * NH_ * NE_ * NE_];
__device__ float g_ctx[(size_t)T_ * O_], g_rel[(size_t)T_ * O_];
__device__ bf16 g_eW1h[(size_t)E_ * D_ * H_], g_eW1l[(size_t)E_ * D_ * H_];
__device__ bf16 g_eW2h[(size_t)E_ * H_ * O_], g_eW2l[(size_t)E_ * H_ * O_];
__device__ bf16 g_Wqh[(size_t)O_ * O_], g_Wql[(size_t)O_ * O_];
__device__ bf16 g_Wkh[(size_t)O_ * O_], g_Wkl[(size_t)O_ * O_];
__device__ bf16 g_Wvh[(size_t)O_ * O_], g_Wvl[(size_t)O_ * O_];
__device__ bf16 g_Woh[(size_t)O_ * O_], g_Wol[(size_t)O_ * O_];
__device__ bf16 g_fW1h[(size_t)O_ * FH_], g_fW1l[(size_t)O_ * FH_];
__device__ bf16 g_fW2h[(size_t)FH_ * O_], g_fW2l[(size_t)FH_ * O_];
__device__ bf16 g_kh[(size_t)T_ * O_], g_kl[(size_t)T_ * O_];
__device__ bf16 g_vth[(size_t)B_ * NH_ * HD_ * NE_], g_vtl[(size_t)B_ * NH_ * HD_ * NE_];

// ---------- helpers ----------
#define SWZ(o) ((o) ^ (((o) >> 3) & 0x70))

__device__ __forceinline__ uint32_t s2u(const void* p) {
    uint32_t a;
    asm("{ .reg .u64 t; cvta.to.shared.u64 t, %1; cvt.u32.u64 %0, t; }" : "=r"(a) : "l"(p));
    return a;
}
__device__ __forceinline__ void split2(float v, bf16& h, bf16& l) {
    h = __float2bfloat16(v);
    l = __float2bfloat16(v - __bfloat162float(h));
}
__device__ __forceinline__ void ldsm4(uint32_t* r, uint32_t addr) {
    asm volatile("ldmatrix.sync.aligned.m8n8.x4.shared.b16 {%0,%1,%2,%3}, [%4];"
                 : "=r"(r[0]), "=r"(r[1]), "=r"(r[2]), "=r"(r[3]) : "r"(addr));
}
__device__ __forceinline__ void mma16816(float* c, const uint32_t* a, const uint32_t* b) {
    asm volatile("mma.sync.aligned.m16n8k16.row.col.f32.bf16.bf16.f32 "
                 "{%0,%1,%2,%3}, {%4,%5,%6,%7}, {%8,%9}, {%0,%1,%2,%3};"
                 : "+f"(c[0]), "+f"(c[1]), "+f"(c[2]), "+f"(c[3])
                 : "r"(a[0]), "r"(a[1]), "r"(a[2]), "r"(a[3]), "r"(b[0]), "r"(b[1]));
}

struct GArgs {
    const float* A; long lda, aSB, aSH;
    const bf16 *Bh, *Bl; long ldk, bSB, bSH, bExp;
    float* C; long ldc, cSB, cSH;
    const float* bias; long biasExp;
    const int* arowIdx; const int* tileE;
    const int* scatTok; const float* scatGw;
    int Kdim, relu, scatter;
};

#define TC_SMEM 133120   // 2048 ctrl + 2 * 65536 stages

// ---------- bf16-split tensor-core GEMM (mma.sync path, sm_103-safe) ----------
// CTA tile 128x128, KC=64, 8 warps (2x4 -> warp tile 64x32), double-buffered.
__global__ void __launch_bounds__(256, 1) tc_gemm(GArgs g)
{
    int e = 0;
    if (g.tileE) { e = g.tileE[blockIdx.y]; if (e < 0) return; }
    extern __shared__ char smem[];
    char* tiles = (char*)((((uintptr_t)smem) + 1024 + 1023) & ~(uintptr_t)1023);
    const int tid = threadIdx.x, wid = tid >> 5, lid = tid & 31;
    int* srow = (int*)smem;                  // 128 ints
    float* sgw = (float*)(smem + 512);       // 128 floats
    const long m0 = (long)blockIdx.y * TM, n0 = (long)blockIdx.x * TN;
    const int z = blockIdx.z, zb = z >> 3, zh = z & 7;

    if (g.arowIdx && tid < TM) srow[tid] = g.arowIdx[m0 + tid];
    if (g.scatter && tid < TM) { srow[tid] = g.scatTok[m0 + tid]; sgw[tid] = g.scatGw[m0 + tid]; }
    __syncthreads();

    const float* Abase = g.A + (size_t)zb * g.aSB + (size_t)zh * g.aSH;
    const bf16* Bhb = g.Bh + (size_t)zb * g.bSB + (size_t)zh * g.bSH + (size_t)e * g.bExp;
    const bf16* Blb = g.Bl + (size_t)zb * g.bSB + (size_t)zh * g.bSH + (size_t)e * g.bExp;

    // global-load pointers (rows fixed, K advances)
    const float4* ap[8]; bool aval[8];
#pragma unroll
    for (int i = 0; i < 8; i++) {
        int f = tid + 256 * i, arow = f >> 4, c4 = f & 15;
        long r;
        if (g.arowIdx) { int tk = srow[arow]; aval[i] = (tk >= 0); r = (tk >= 0) ? tk : 0; }
        else { aval[i] = true; r = m0 + arow; }
        ap[i] = (const float4*)(Abase + (size_t)r * g.lda) + c4;
    }
    const uint4* bp[8];
#pragma unroll
    for (int i = 0; i < 4; i++) {
        int f = tid + 256 * i, brow = f >> 3, c16 = f & 7;
        size_t boff = (size_t)(n0 + brow) * g.ldk + (size_t)c16 * 8;
        bp[i] = (const uint4*)(Bhb + boff);
        bp[i + 4] = (const uint4*)(Blb + boff);
    }

    float4 pa[8]; uint4 pb[8];
    auto loadregs = [&](int kc) {
        size_t o4 = (size_t)16 * kc, o16 = (size_t)8 * kc;
#pragma unroll
        for (int i = 0; i < 8; i++) pa[i] = aval[i] ? ap[i][o4] : make_float4(0.f, 0.f, 0.f, 0.f);
#pragma unroll
        for (int i = 0; i < 8; i++) pb[i] = bp[i][o16];
    };
    auto sts = [&](int s) {
        char* st = tiles + s * 65536;
#pragma unroll
        for (int i = 0; i < 8; i++) {
            int f = tid + 256 * i, arow = f >> 4, c4 = f & 15;
            int sw = SWZ(arow * 128 + c4 * 8);
            bf16 h0, l0, h1, l1, h2, l2, h3, l3;
            split2(pa[i].x, h0, l0); split2(pa[i].y, h1, l1);
            split2(pa[i].z, h2, l2); split2(pa[i].w, h3, l3);
            __nv_bfloat162 hA = __halves2bfloat162(h0, h1), hB = __halves2bfloat162(h2, h3);
            __nv_bfloat162 lA = __halves2bfloat162(l0, l1), lB = __halves2bfloat162(l2, l3);
            *(uint2*)(st + sw) = make_uint2(*(uint32_t*)&hA, *(uint32_t*)&hB);
            *(uint2*)(st + 16384 + sw) = make_uint2(*(uint32_t*)&lA, *(uint32_t*)&lB);
        }
#pragma unroll
        for (int i = 0; i < 4; i++) {
            int f = tid + 256 * i, brow = f >> 3, c16 = f & 7;
            int sw = SWZ(brow * 128 + c16 * 16);
            *(uint4*)(st + 32768 + sw) = pb[i];
            *(uint4*)(st + 49152 + sw) = pb[i + 4];
        }
    };

    const uint32_t tilesU = s2u(tiles);
    const int wm = wid >> 2, wn = wid & 3;        // 2x4 warp grid
    const int m_w = wm * 64, n_w = wn * 32;
    const int jj = lid >> 3, rr = lid & 7;

    float acc[4][4][4];
#pragma unroll
    for (int a = 0; a < 4; a++)
#pragma unroll
        for (int b = 0; b < 4; b++)
#pragma unroll
            for (int c = 0; c < 4; c++) acc[a][b][c] = 0.f;

    auto compute = [&](int s) {
        uint32_t base = tilesU + s * 65536;
#pragma unroll
        for (int k16 = 0; k16 < 4; k16++) {
            int kk = k16 * 16;
            uint32_t Ah[4][4], Al[4][4];
#pragma unroll
            for (int mf = 0; mf < 4; mf++) {
                int row = m_w + mf * 16 + (jj & 1) * 8 + rr;
                int kb = (kk + (jj >> 1) * 8) * 2;
                uint32_t off = (uint32_t)(row * 128 + (kb ^ ((row & 7) * 16)));
                ldsm4(Ah[mf], base + off);
                ldsm4(Al[mf], base + 16384 + off);
            }
            uint32_t Bh[2][4], Bl[2][4];
#pragma unroll
            for (int np = 0; np < 2; np++) {
                int row = n_w + np * 16 + (jj >> 1) * 8 + rr;
                int kb = (kk + (jj & 1) * 8) * 2;
                uint32_t off = (uint32_t)(row * 128 + (kb ^ ((row & 7) * 16)));
                ldsm4(Bh[np], base + 32768 + off);
                ldsm4(Bl[np], base + 49152 + off);
            }
#pragma unroll
            for (int mf = 0; mf < 4; mf++)
#pragma unroll
                for (int nf = 0; nf < 4; nf++) {
                    uint32_t* bh = &Bh[nf >> 1][(nf & 1) * 2];
                    uint32_t* bl = &Bl[nf >> 1][(nf & 1) * 2];
                    float* c = acc[mf][nf];
                    mma16816(c, Ah[mf], bh);
                    mma16816(c, Ah[mf], bl);
                    mma16816(c, Al[mf], bh);
                }
        }
    };

    const int nC = g.Kdim >> 6;
    loadregs(0);
    sts(0);
    __syncthreads();
    for (int kc = 0; kc < nC; kc++) {
        if (kc + 1 < nC) loadregs(kc + 1);
        compute(kc & 1);
        if (kc + 1 < nC) {
            sts((kc + 1) & 1);
            __syncthreads();
        }
    }

    // ---------- epilogue ----------
    const float* biasp = g.bias ? (g.bias + (size_t)e * g.biasExp + n0) : (const float*)0;
    size_t cbase = (size_t)zb * g.cSB + (size_t)zh * g.cSH;
#pragma unroll
    for (int mf = 0; mf < 4; mf++) {
#pragma unroll
        for (int half = 0; half < 2; half++) {
            int mrow = m_w + mf * 16 + (lid >> 2) + half * 8;
            long gm = m0 + mrow;
            if (g.scatter) {
                int tok = srow[mrow];
                if (tok < 0) continue;
                float gw = sgw[mrow];
                float* Cr = g.C + (size_t)tok * g.ldc + n0;
#pragma unroll
                for (int nf = 0; nf < 4; nf++) {
                    int col = n_w + nf * 8 + (lid & 3) * 2;
                    float v0 = acc[mf][nf][half * 2 + 0];
                    float v1 = acc[mf][nf][half * 2 + 1];
                    if (biasp) { v0 += biasp[col]; v1 += biasp[col + 1]; }
                    atomicAdd(&Cr[col], gw * v0);
                    atomicAdd(&Cr[col + 1], gw * v1);
                }
            } else {
                float* Cr = g.C + cbase + (size_t)gm * g.ldc + n0;
#pragma unroll
                for (int nf = 0; nf < 4; nf++) {
                    int col = n_w + nf * 8 + (lid & 3) * 2;
                    float v0 = acc[mf][nf][half * 2 + 0];
                    float v1 = acc[mf][nf][half * 2 + 1];
                    if (biasp) { v0 += biasp[col]; v1 += biasp[col + 1]; }
                    if (g.relu) { v0 = fmaxf(v0, 0.f); v1 = fmaxf(v1, 0.f); }
                    Cr[col] = v0;
                    Cr[col + 1] = v1;
                }
            }
        }
    }
}

// ---------- weight transpose+split: W[K,N](fp32) -> Wt[N,K] hi/lo ----------
__global__ void wsplit(const float* __restrict__ W, bf16* __restrict__ oh,
                       bf16* __restrict__ ol, int K, int N)
{
    __shared__ float t[32][33];
    size_t zoff = (size_t)blockIdx.z * K * N;
    W += zoff; oh += zoff; ol += zoff;
    int n0 = blockIdx.x * 32, k0 = blockIdx.y * 32;
    int tx = threadIdx.x, ty = threadIdx.y;
#pragma unroll
    for (int r = 0; r < 4; r++)
        t[ty + r * 8][tx] = W[(size_t)(k0 + ty + r * 8) * N + n0 + tx];
    __syncthreads();
#pragma unroll
    for (int r = 0; r < 4; r++) {
        int n = n0 + ty + r * 8, k = k0 + tx;
        bf16 h, l; split2(t[tx][ty + r * 8], h, l);
        oh[(size_t)n * K + k] = h; ol[(size_t)n * K + k] = l;
    }
}

__global__ void esplit(const float* __restrict__ s, bf16* __restrict__ oh,
                       bf16* __restrict__ ol, size_t n)
{
    size_t i = (size_t)blockIdx.x * blockDim.x + threadIdx.x;
    size_t st = (size_t)gridDim.x * blockDim.x;
    for (; i < n; i += st) { bf16 h, l; split2(s[i], h, l); oh[i] = h; ol[i] = l; }
}

__global__ void vtsplit()
{
    __shared__ float t[32][33];
    int bh = blockIdx.z, b = bh >> 3, h = bh & 7;
    int m0 = blockIdx.x * 32, d0 = blockIdx.y * 32;
    int tx = threadIdx.x, ty = threadIdx.y;
#pragma unroll
    for (int r = 0; r < 4; r++)
        t[ty + r * 8][tx] = g_v[((size_t)b * NE_ + m0 + ty + r * 8) * O_ + h * HD_ + d0 + tx];
    __syncthreads();
#pragma unroll
    for (int r = 0; r < 4; r++) {
        int d = d0 + ty + r * 8, m = m0 + tx;
        bf16 h2, l2; split2(t[tx][ty + r * 8], h2, l2);
        size_t o = ((size_t)bh * HD_ + d) * NE_ + m;
        g_vth[o] = h2; g_vtl[o] = l2;
    }
}

__global__ void init_kernel()
{
    size_t i = (size_t)blockIdx.x * blockDim.x + threadIdx.x;
    size_t st = (size_t)gridDim.x * blockDim.x;
    for (size_t j = i; j < (size_t)T_ * O_; j += st) g_ent[j] = 0.f;
    for (size_t j = i; j < (size_t)SLOTMAX; j += st) g_slot_tok[j] = -1;
    if (i < E_) { g_cnt[i] = 0; g_fill[i] = 0; }
}

__global__ void __launch_bounds__(256) pool_kernel(const float* __restrict__ x,
                                                   const float* __restrict__ attn_w)
{
    const int t = blockIdx.x, tid = threadIdx.x;
    const float* base = x + (size_t)t * NO_ * D_;
    float4 aw = ((const float4*)attn_w)[tid];
    float p[NO_];
#pragma unroll
    for (int o = 0; o < NO_; o++) {
        float4 xv = ((const float4*)(base + (size_t)o * D_))[tid];
        p[o] = xv.x * aw.x + xv.y * aw.y + xv.z * aw.z + xv.w * aw.w;
    }
#pragma unroll
    for (int off = 16; off; off >>= 1)
#pragma unroll
        for (int o = 0; o < NO_; o++) p[o] += __shfl_down_sync(0xffffffffu, p[o], off);
    __shared__ float sm[NO_][8], wsh[NO_];
    const int w = tid >> 5;
    if ((tid & 31) == 0)
#pragma unroll
        for (int o = 0; o < NO_; o++) sm[o][w] = p[o];
    __syncthreads();
    if (tid == 0) {
        float l[NO_];
#pragma unroll
        for (int o = 0; o < NO_; o++) {
            float s = 0.f;
#pragma unroll
            for (int ww = 0; ww < 8; ww++) s += sm[o][ww];
            l[o] = s;
        }
        float mx = l[0];
#pragma unroll
        for (int o = 1; o < NO_; o++) mx = fmaxf(mx, l[o]);
        float ss = 0.f;
#pragma unroll
        for (int o = 0; o < NO_; o++) { float ev = expf(l[o] - mx); wsh[o] = ev; ss += ev; }
        float inv = 1.f / ss;
#pragma unroll
        for (int o = 0; o < NO_; o++) wsh[o] *= inv;
    }
    __syncthreads();
    float4 ov = make_float4(0.f, 0.f, 0.f, 0.f);
#pragma unroll
    for (int o = 0; o < NO_; o++) {
        float4 xv = ((const float4*)(base + (size_t)o * D_))[tid];
        float wo = wsh[o];
        ov.x = fmaf(wo, xv.x, ov.x); ov.y = fmaf(wo, xv.y, ov.y);
        ov.z = fmaf(wo, xv.z, ov.z); ov.w = fmaf(wo, xv.w, ov.w);
    }
    ((float4*)(g_xagg + (size_t)t * D_))[tid] = ov;
}

__global__ void __launch_bounds__(256) gate_kernel(const float* __restrict__ gW,
                                                   const float* __restrict__ gb)
{
    const int t = blockIdx.x, tid = threadIdx.x;
    float4 xv = ((const float4*)(g_xagg + (size_t)t * D_))[tid];
    float xs[4] = {xv.x, xv.y, xv.z, xv.w};
    const float* gr = gW + (size_t)tid * 4 * E_;
    float acc[E_];
#pragma unroll
    for (int e = 0; e < E_; e++) acc[e] = 0.f;
#pragma unroll
    for (int r = 0; r < 4; r++) {
        float4 w0 = *(const float4*)(gr + r * E_);
        float4 w1 = *(const float4*)(gr + r * E_ + 4);
        acc[0] = fmaf(xs[r], w0.x, acc[0]); acc[1] = fmaf(xs[r], w0.y, acc[1]);
        acc[2] = fmaf(xs[r], w0.z, acc[2]); acc[3] = fmaf(xs[r], w0.w, acc[3]);
        acc[4] = fmaf(xs[r], w1.x, acc[4]); acc[5] = fmaf(xs[r], w1.y, acc[5]);
        acc[6] = fmaf(xs[r], w1.z, acc[6]); acc[7] = fmaf(xs[r], w1.w, acc[7]);
    }
#pragma unroll
    for (int off = 16; off; off >>= 1)
#pragma unroll
        for (int e = 0; e < E_; e++) acc[e] += __shfl_down_sync(0xffffffffu, acc[e], off);
    __shared__ float sm[E_][8];
    const int w = tid >> 5;
    if ((tid & 31) == 0)
#pragma unroll
        for (int e = 0; e < E_; e++) sm[e][w] = acc[e];
    __syncthreads();
    if (tid == 0) {
        float l[E_];
#pragma unroll
        for (int e = 0; e < E_; e++) {
            float s = gb[e];
#pragma unroll
            for (int ww = 0; ww < 8; ww++) s += sm[e][ww];
            l[e] = s;
        }
        int i0 = 0;
#pragma unroll
        for (int e = 1; e < E_; e++) if (l[e] > l[i0]) i0 = e;
        int i1 = -1;
#pragma unroll
        for (int e = 0; e < E_; e++) if (e != i0 && (i1 < 0 || l[e] > l[i1])) i1 = e;
        float g0 = 1.f / (1.f + expf(l[i1] - l[i0]));
        g_topi[2 * t] = i0; g_topi[2 * t + 1] = i1;
        g_gate[2 * t] = g0; g_gate[2 * t + 1] = 1.f - g0;
        atomicAdd(&g_cnt[i0], 1); atomicAdd(&g_cnt[i1], 1);
    }
}

__global__ void scan_kernel()
{
    if (threadIdx.x == 0 && blockIdx.x == 0) {
        int off = 0;
        for (int e = 0; e < E_; e++) {
            g_off[e] = off;
            int tiles = (g_cnt[e] + TM - 1) / TM;
            for (int tt = 0; tt < tiles; tt++) g_tile_e[off / TM + tt] = e;
            off += tiles * TM;
        }
        g_off[E_] = off;
        for (int tt = off / TM; tt < MAXTILES; tt++) g_tile_e[tt] = -1;
    }
}

__global__ void place_kernel()
{
    int t = blockIdx.x * blockDim.x + threadIdx.x;
    if (t >= T_) return;
#pragma unroll
    for (int j = 0; j < 2; j++) {
        int e = g_topi[2 * t + j];
        int pos = atomicAdd(&g_fill[e], 1);
        int s = g_off[e] + pos;
        g_slot_tok[s] = t;
        g_slot_gw[s] = g_gate[2 * t + j];
    }
}

__global__ void __launch_bounds__(256) attn_softmax_kernel()
{
    const int tid = threadIdx.x;
    float* row = g_scores + (size_t)blockIdx.x * NE_;
    float4 v = ((float4*)row)[tid];
    const float sc = 0.08838834764831845f;
    v.x *= sc; v.y *= sc; v.z *= sc; v.w *= sc;
    float m = fmaxf(fmaxf(v.x, v.y), fmaxf(v.z, v.w));
#pragma unroll
    for (int off = 16; off; off >>= 1) m = fmaxf(m, __shfl_xor_sync(0xffffffffu, m, off));
    __shared__ float sr[8];
    const int w = tid >> 5;
    if ((tid & 31) == 0) sr[w] = m;
    __syncthreads();
    float gm = sr[0];
#pragma unroll
    for (int i = 1; i < 8; i++) gm = fmaxf(gm, sr[i]);
    float e0 = expf(v.x - gm), e1 = expf(v.y - gm), e2 = expf(v.z - gm), e3 = expf(v.w - gm);
    float s = e0 + e1 + e2 + e3;
#pragma unroll
    for (int off = 16; off; off >>= 1) s += __shfl_xor_sync(0xffffffffu, s, off);
    __syncthreads();
    if ((tid & 31) == 0) sr[w] = s;
    __syncthreads();
    float gs = 0.f;
#pragma unroll
    for (int i = 0; i < 8; i++) gs += sr[i];
    float inv = 1.f / gs;
    ((float4*)row)[tid] = make_float4(e0 * inv, e1 * inv, e2 * inv, e3 * inv);
}

// ---------- host ----------
#define SYM(p, s) do { void* _t; cudaGetSymbolAddress(&_t, s); p = (decltype(p))_t; } while (0)

static GArgs ga(const float* A, long lda, const bf16* Bh, const bf16* Bl, long ldk,
                float* C, long ldc, int Kdim, const float* bias)
{
    GArgs g = {};
    g.A = A; g.lda = lda; g.Bh = Bh; g.Bl = Bl; g.ldk = ldk;
    g.C = C; g.ldc = ldc; g.Kdim = Kdim; g.bias = bias;
    return g;
}

extern "C" void kernel_launch(void* const* d_in, const int* in_sizes, int n_in,
                              void* d_out, int out_size)
{
    const float* x      = (const float*)d_in[0];
    const float* attn_w = (const float*)d_in[1];
    const float* gate_W = (const float*)d_in[2];
    const float* gate_b = (const float*)d_in[3];
    const float* eW1 = (const float*)d_in[4];
    const float* eb1 = (const float*)d_in[5];
    const float* eW2 = (const float*)d_in[6];
    const float* eb2 = (const float*)d_in[7];
    const float* Wq = (const float*)d_in[8];
    const float* bq = (const float*)d_in[9];
    const float* Wk = (const float*)d_in[10];
    const float* bk = (const float*)d_in[11];
    const float* Wv = (const float*)d_in[12];
    const float* bv = (const float*)d_in[13];
    const float* Wo = (const float*)d_in[14];
    const float* bo = (const float*)d_in[15];
    const float* fW1 = (const float*)d_in[16];
    const float* fb1 = (const float*)d_in[17];
    const float* fW2 = (const float*)d_in[18];
    const float* fb2 = (const float*)d_in[19];
    float* out = (float*)d_out;

    float *p_xagg, *p_ent, *p_hbuf, *p_q, *p_k, *p_v, *p_scores, *p_ctx, *p_rel;
    int *p_slot_tok, *p_tile_e; float* p_slot_gw;
    bf16 *p_eW1h, *p_eW1l, *p_eW2h, *p_eW2l, *p_Wqh, *p_Wql, *p_Wkh, *p_Wkl;
    bf16 *p_Wvh, *p_Wvl, *p_Woh, *p_Wol, *p_fW1h, *p_fW1l, *p_fW2h, *p_fW2l;
    bf16 *p_kh, *p_kl, *p_vth, *p_vtl;
    SYM(p_xagg, g_xagg); SYM(p_ent, g_ent); SYM(p_hbuf, g_hbuf);
    SYM(p_q, g_q); SYM(p_k, g_k); SYM(p_v, g_v);
    SYM(p_scores, g_scores); SYM(p_ctx, g_ctx); SYM(p_rel, g_rel);
    SYM(p_slot_tok, g_slot_tok); SYM(p_tile_e, g_tile_e); SYM(p_slot_gw, g_slot_gw);
    SYM(p_eW1h, g_eW1h); SYM(p_eW1l, g_eW1l); SYM(p_eW2h, g_eW2h); SYM(p_eW2l, g_eW2l);
    SYM(p_Wqh, g_Wqh); SYM(p_Wql, g_Wql); SYM(p_Wkh, g_Wkh); SYM(p_Wkl, g_Wkl);
    SYM(p_Wvh, g_Wvh); SYM(p_Wvl, g_Wvl); SYM(p_Woh, g_Woh); SYM(p_Wol, g_Wol);
    SYM(p_fW1h, g_fW1h); SYM(p_fW1l, g_fW1l); SYM(p_fW2h, g_fW2h); SYM(p_fW2l, g_fW2l);
    SYM(p_kh, g_kh); SYM(p_kl, g_kl); SYM(p_vth, g_vth); SYM(p_vtl, g_vtl);

    cudaFuncSetAttribute(tc_gemm, cudaFuncAttributeMaxDynamicSharedMemorySize, TC_SMEM);
    dim3 tb(32, 8);

    init_kernel<<<4096, 256>>>();
    // weight transpose+split
    wsplit<<<dim3(H_ / 32, D_ / 32, E_), tb>>>(eW1, p_eW1h, p_eW1l, D_, H_);
    wsplit<<<dim3(O_ / 32, H_ / 32, E_), tb>>>(eW2, p_eW2h, p_eW2l, H_, O_);
    wsplit<<<dim3(O_ / 32, O_ / 32, 1), tb>>>(Wq, p_Wqh, p_Wql, O_, O_);
    wsplit<<<dim3(O_ / 32, O_ / 32, 1), tb>>>(Wk, p_Wkh, p_Wkl, O_, O_);
    wsplit<<<dim3(O_ / 32, O_ / 32, 1), tb>>>(Wv, p_Wvh, p_Wvl, O_, O_);
    wsplit<<<dim3(O_ / 32, O_ / 32, 1), tb>>>(Wo, p_Woh, p_Wol, O_, O_);
    wsplit<<<dim3(FH_ / 32, O_ / 32, 1), tb>>>(fW1, p_fW1h, p_fW1l, O_, FH_);
    wsplit<<<dim3(O_ / 32, FH_ / 32, 1), tb>>>(fW2, p_fW2h, p_fW2l, FH_, O_);
    // pooling + routing
    pool_kernel<<<T_, 256>>>(x, attn_w);
    gate_kernel<<<T_, 256>>>(gate_W, gate_b);
    scan_kernel<<<1, 32>>>();
    place_kernel<<<(T_ + 255) / 256, 256>>>();
    // MoE expert GEMMs
    {
        GArgs g = ga(p_xagg, D_, p_eW1h, p_eW1l, D_, p_hbuf, H_, D_, eb1);
        g.biasExp = H_; g.relu = 1; g.arowIdx = p_slot_tok; g.tileE = p_tile_e;
        g.bExp = (long)D_ * H_;
        tc_gemm<<<dim3(H_ / TN, MAXTILES), 256, TC_SMEM>>>(g);
    }
    {
        GArgs g = ga(p_hbuf, H_, p_eW2h, p_eW2l, H_, p_ent, O_, H_, eb2);
        g.biasExp = O_; g.tileE = p_tile_e; g.bExp = (long)H_ * O_;
        g.scatter = 1; g.scatTok = p_slot_tok; g.scatGw = p_slot_gw;
        tc_gemm<<<dim3(O_ / TN, MAXTILES), 256, TC_SMEM>>>(g);
    }
    // QKV projections
    tc_gemm<<<dim3(O_ / TN, T_ / TM), 256, TC_SMEM>>>(ga(p_ent, O_, p_Wqh, p_Wql, O_, p_q, O_, O_, bq));
    tc_gemm<<<dim3(O_ / TN, T_ / TM), 256, TC_SMEM>>>(ga(p_ent, O_, p_Wkh, p_Wkl, O_, p_k, O_, O_, bk));
    tc_gemm<<<dim3(O_ / TN, T_ / TM), 256, TC_SMEM>>>(ga(p_ent, O_, p_Wvh, p_Wvl, O_, p_v, O_, O_, bv));
    esplit<<<4096, 256>>>(p_k, p_kh, p_kl, (size_t)T_ * O_);
    vtsplit<<<dim3(NE_ / 32, HD_ / 32, B_ * NH_), tb>>>();
    // scores = q @ k^T   (Kdim = HD = 128 -> nC = 2)
    {
        GArgs g = ga(p_q, O_, p_kh, p_kl, O_, p_scores, NE_, HD_, 0);
        g.aSB = (long)NE_ * O_; g.aSH = HD_;
        g.bSB = (long)NE_ * O_; g.bSH = HD_;
        g.cSB = (long)NH_ * NE_ * NE_; g.cSH = (long)NE_ * NE_;
        tc_gemm<<<dim3(NE_ / TN, NE_ / TM, B_ * NH_), 256, TC_SMEM>>>(g);
    }
    attn_softmax_kernel<<<B_ * NH_ * NE_, 256>>>();
    // ctx = attn @ v
    {
        GArgs g = ga(p_scores, NE_, p_vth, p_vtl, NE_, p_ctx, O_, NE_, 0);
        g.aSB = (long)NH_ * NE_ * NE_; g.aSH = (long)NE_ * NE_;
        g.bSB = (long)NH_ * HD_ * NE_; g.bSH = (long)HD_ * NE_;
        g.cSB = (long)NE_ * O_; g.cSH = HD_;
        tc_gemm<<<dim3(1, NE_ / TM, B_ * NH_), 256, TC_SMEM>>>(g);
    }
    // Wo + FFN
    tc_gemm<<<dim3(O_ / TN, T_ / TM), 256, TC_SMEM>>>(ga(p_ctx, O_, p_Woh, p_Wol, O_, p_rel, O_, O_, bo));
    {
        GArgs g = ga(p_rel, O_, p_fW1h, p_fW1l, O_, p_hbuf, FH_, O_, fb1);
        g.relu = 1;
        tc_gemm<<<dim3(FH_ / TN, T_ / TM), 256, TC_SMEM>>>(g);
    }
    tc_gemm<<<dim3(O_ / TN, T_ / TM), 256, TC_SMEM>>>(ga(p_hbuf, FH_, p_fW2h, p_fW2l, FH_, out, O_, FH_, fb2));
}